// round 15
// baseline (speedup 1.0000x reference)
#include <cuda_runtime.h>
#include <cuda_fp16.h>
#include <cstdint>
#include <cstring>

#define N_NODES 50000
#define N_PAD   50048            // padded rows: 782 full 64-row tiles
#define N_EDGES 640000
#define F 128
#define N_TILES 782              // 64-row tiles
#define BKT_CAP 128

typedef unsigned long long ull;

__device__ __forceinline__ uint32_t h2u(__half2 h) {
    uint32_t u;
    memcpy(&u, &h, 4);
    return u;
}

// Scratch (device globals). x/mean padded so tail-tile cp.async stays in-bounds.
__device__ __align__(256) __half g_xh[(size_t)N_PAD * F];        // x hi (fp16)
__device__ __align__(256) __half g_mh[(size_t)N_PAD * F];        // mean hi
__device__ __align__(256) int    g_bucket[(size_t)N_NODES * BKT_CAP];
__device__ __align__(256) int    g_deg[N_NODES];
__device__ __align__(256) __half g_Wt_hi[128 * 256];             // W^T hi
__device__ __align__(256) __half g_Wt_lo[128 * 256];             // W^T lo
__device__ int g_idx64;

// ---------------------------------------------------------------------------
// prep_all: fused detect + zero_deg + prep_w + prep_x(hi only).
// ---------------------------------------------------------------------------
__global__ void __launch_bounds__(256) prep_all_kernel(
    const float* __restrict__ x,
    const int* __restrict__ e,
    const float* __restrict__ Wl,
    const float* __restrict__ Wr)
{
    const int tid = threadIdx.x;
    const int bid = blockIdx.x;
    const int gi  = bid * 256 + tid;

    if (bid == 6249 && tid == 0) {
        int nz = 0;
        #pragma unroll 8
        for (int i = 0; i < 256; i++) nz |= e[2 * i + 1];
        g_idx64 = (nz == 0) ? 1 : 0;
    }
    if (gi < N_NODES) g_deg[gi] = 0;
    if (bid < 128) {
        int n = bid, k = tid;
        float v  = (k < 128) ? Wl[k * 128 + n] : Wr[(k - 128) * 128 + n];
        __half h = __float2half_rn(v);
        __half l = __float2half_rn(v - __half2float(h));
        g_Wt_hi[n * 256 + k] = h;
        g_Wt_lo[n * 256 + k] = l;
    }
    {
        float4 v = ((const float4*)x)[gi];
        __half2 h01 = __floats2half2_rn(v.x, v.y);
        __half2 h23 = __floats2half2_rn(v.z, v.w);
        uint2 sh;
        sh.x = h2u(h01); sh.y = h2u(h23);
        ((uint2*)g_xh)[gi] = sh;
    }
}

// ---------------------------------------------------------------------------
// Bucket fill: 8 edges per thread (independent atomic chains for MLP).
// ---------------------------------------------------------------------------
__global__ void __launch_bounds__(256) fill_kernel(const void* __restrict__ eidx) {
    int base = blockIdx.x * 2048 + threadIdx.x;
    const int idx64 = g_idx64;
    #pragma unroll
    for (int j = 0; j < 8; j++) {
        int e = base + j * 256;
        if (e >= N_EDGES) return;
        int src, dst;
        if (idx64) {
            const long long* p = (const long long*)eidx;
            src = (int)p[e];
            dst = (int)p[N_EDGES + e];
        } else {
            const int* p = (const int*)eidx;
            src = p[e];
            dst = p[N_EDGES + e];
        }
        int pos = atomicAdd(&g_deg[dst], 1);
        if (pos < BKT_CAP) g_bucket[(size_t)dst * BKT_CAP + pos] = src;
    }
}

// ---------------------------------------------------------------------------
// Gather: one warp per node; half-warps process even/odd neighbors, combine
// via shfl_xor(16); sub0 writes the fp16 mean (hi only).
// ---------------------------------------------------------------------------
__global__ void __launch_bounds__(256) gather_kernel() {
    int node = (blockIdx.x * 256 + threadIdx.x) >> 5;
    int lane = threadIdx.x & 31;
    if (node >= N_NODES) return;

    int deg = g_deg[node];
    int d   = min(deg, BKT_CAP);
    const int* bkt = g_bucket + (size_t)node * BKT_CAP;

    const int hl  = lane & 15;
    const int sub = lane >> 4;

    float a[8]  = {0.f, 0.f, 0.f, 0.f, 0.f, 0.f, 0.f, 0.f};
    float a2[8] = {0.f, 0.f, 0.f, 0.f, 0.f, 0.f, 0.f, 0.f};

    auto add8 = [&](float* acc, uint4 u) {
        const uint32_t w[4] = {u.x, u.y, u.z, u.w};
        #pragma unroll
        for (int p = 0; p < 4; p++) {
            __half2 hp;
            memcpy(&hp, &w[p], 4);
            float2 f = __half22float2(hp);
            acc[2 * p]     += f.x;
            acc[2 * p + 1] += f.y;
        }
    };

    for (int base = 0; base < d; base += 32) {
        int cnt = min(32, d - base);
        int s = (lane < cnt) ? bkt[base + lane] : 0;
        int j = 0;
        for (; j + 4 <= cnt; j += 4) {
            int sA = __shfl_sync(0xFFFFFFFFu, s, j + sub);
            int sB = __shfl_sync(0xFFFFFFFFu, s, j + 2 + sub);
            uint4 vA = *(const uint4*)(g_xh + (size_t)sA * F + hl * 8);
            uint4 vB = *(const uint4*)(g_xh + (size_t)sB * F + hl * 8);
            add8(a, vA);
            add8(a2, vB);
        }
        for (; j + 2 <= cnt; j += 2) {
            int sA = __shfl_sync(0xFFFFFFFFu, s, j + sub);
            uint4 vA = *(const uint4*)(g_xh + (size_t)sA * F + hl * 8);
            add8(a, vA);
        }
        if (j < cnt) {
            int sA = __shfl_sync(0xFFFFFFFFu, s, j);
            if (sub == 0) {
                uint4 vA = *(const uint4*)(g_xh + (size_t)sA * F + hl * 8);
                add8(a, vA);
            }
        }
    }

    float inv = 1.f / fmaxf((float)deg, 1.f);
    uint32_t outw[4];
    #pragma unroll
    for (int p = 0; p < 4; p++) {
        float v0 = a[2 * p] + a2[2 * p];
        float v1 = a[2 * p + 1] + a2[2 * p + 1];
        v0 += __shfl_xor_sync(0xFFFFFFFFu, v0, 16);
        v1 += __shfl_xor_sync(0xFFFFFFFFu, v1, 16);
        outw[p] = h2u(__floats2half2_rn(v0 * inv, v1 * inv));
    }
    if (sub == 0)
        *(uint4*)(g_mh + (size_t)node * F + hl * 8) =
            make_uint4(outw[0], outw[1], outw[2], outw[3]);
}

// ---------------------------------------------------------------------------
// 2-pass FP16 mma.sync GEMM: out = relu(A_hi @ (W_hi + W_lo)^T + b)
// Tile 64m x 128n, K chunks of 32 (8 chunks), 256 threads = 8 warps (32x32).
// 50.5 KB smem + <=64 regs -> 4 CTAs/SM (32 warps, full regfile).
// ---------------------------------------------------------------------------
#define STRIDE_C 80                 // bytes per smem row (32 halves + 16B pad)
#define BUF_A    (64 * STRIDE_C)    // 5120 B
#define BUF_B    (128 * STRIDE_C)   // 10240 B
#define OFF_BIAS 0
#define OFF_A0   512
#define OFF_A1   (OFF_A0 + BUF_A)
#define OFF_BH0  (OFF_A1 + BUF_A)
#define OFF_BL0  (OFF_BH0 + BUF_B)
#define OFF_BH1  (OFF_BL0 + BUF_B)
#define OFF_BL1  (OFF_BH1 + BUF_B)
#define GEMM_SMEM (OFF_BL1 + BUF_B)   // 51712 B

#define MMAH(c, a, bb) \
    asm("mma.sync.aligned.m16n8k16.row.col.f32.f16.f16.f32 " \
        "{%0,%1,%2,%3}, {%4,%5,%6,%7}, {%8,%9}, {%0,%1,%2,%3};" \
        : "+f"((c)[0]), "+f"((c)[1]), "+f"((c)[2]), "+f"((c)[3]) \
        : "r"((a)[0]), "r"((a)[1]), "r"((a)[2]), "r"((a)[3]), \
          "r"((bb)[0]), "r"((bb)[1]))

#define LDSM4(r0, r1, r2, r3, addr) \
    asm volatile("ldmatrix.sync.aligned.m8n8.x4.shared.b16 {%0,%1,%2,%3}, [%4];" \
        : "=r"(r0), "=r"(r1), "=r"(r2), "=r"(r3) : "r"(addr))

__device__ __forceinline__ uint32_t smem_u32(const void* p) {
    uint32_t a;
    asm("{ .reg .u64 t; cvta.to.shared.u64 t, %1; cvt.u32.u64 %0, t; }" : "=r"(a) : "l"(p));
    return a;
}
__device__ __forceinline__ void cp16(uint32_t s, const void* g) {
    asm volatile("cp.async.cg.shared.global [%0], [%1], 16;" :: "r"(s), "l"(g));
}

extern __shared__ char gsm[];

__global__ void __launch_bounds__(256, 4) gemm_kernel(
    const float* __restrict__ b,
    float* __restrict__ out)
{
    const int tid  = threadIdx.x;
    const int wid  = tid >> 5;
    const int lane = tid & 31;
    const int row0 = blockIdx.x * 64;
    const int q    = lane >> 2;
    const int tg   = lane & 3;

    const int wm = wid & 1;          // m block (x32), 0..1
    const int wn = wid >> 1;         // n block (x32), 0..3

    float* sBias = (float*)(gsm + OFF_BIAS);
    if (tid < 128) sBias[tid] = b[tid];

    const uint32_t sbase = smem_u32(gsm);

    // ldmatrix per-lane offsets.
    const int mat = lane >> 3;
    const int mr  = lane & 7;
    uint32_t aoff[2], boff[2];
    #pragma unroll
    for (int mt = 0; mt < 2; mt++) {
        int r = wm * 32 + mt * 16 + (mat & 1) * 8 + mr;
        aoff[mt] = (uint32_t)r * STRIDE_C + (mat >> 1) * 16;
    }
    #pragma unroll
    for (int p = 0; p < 2; p++) {
        int r = wn * 32 + p * 16 + (mat >> 1) * 8 + mr;
        boff[p] = (uint32_t)r * STRIDE_C + (mat & 1) * 16;
    }

    // Stage one K32 chunk: A 64 rows (256 cp16), Bh/Bl 128 rows (512 each).
    auto stage_chunk = [&](int kc, int buf) {
        const uint32_t dA  = sbase + (buf ? OFF_A1 : OFF_A0);
        const uint32_t dBh = sbase + (buf ? OFF_BH1 : OFF_BH0);
        const uint32_t dBl = sbase + (buf ? OFF_BL1 : OFF_BL0);
        const __half* srcA = (kc < 4) ? g_mh : g_xh;
        const int cb = (kc & 3) * 32;
        {
            int r  = tid >> 2;          // 0..63
            int c4 = tid & 3;
            cp16(dA + (uint32_t)r * STRIDE_C + c4 * 16,
                 srcA + (size_t)(row0 + r) * F + cb + c4 * 8);
        }
        #pragma unroll
        for (int j = 0; j < 2; j++) {
            int idx = tid + j * 256;    // 0..511
            int r   = idx >> 2;         // 0..127
            int c4  = idx & 3;
            uint32_t doff = (uint32_t)r * STRIDE_C + c4 * 16;
            cp16(dBh + doff, g_Wt_hi + (size_t)r * 256 + kc * 32 + c4 * 8);
            cp16(dBl + doff, g_Wt_lo + (size_t)r * 256 + kc * 32 + c4 * 8);
        }
        asm volatile("cp.async.commit_group;" ::: "memory");
    };

    stage_chunk(0, 0);
    stage_chunk(1, 1);

    float acc[2][4][4];
    #pragma unroll
    for (int mt = 0; mt < 2; mt++)
        #pragma unroll
        for (int nt = 0; nt < 4; nt++)
            #pragma unroll
            for (int r = 0; r < 4; r++) acc[mt][nt][r] = 0.f;

    for (int kc = 0; kc < 8; kc++) {
        const int buf = kc & 1;
        if (kc < 7) {
            asm volatile("cp.async.wait_group 1;" ::: "memory");
        } else {
            asm volatile("cp.async.wait_group 0;" ::: "memory");
        }
        __syncthreads();

        const uint32_t sA  = sbase + (buf ? OFF_A1 : OFF_A0);
        const uint32_t sBh = sbase + (buf ? OFF_BH1 : OFF_BH0);
        const uint32_t sBl = sbase + (buf ? OFF_BL1 : OFF_BL0);

        // 2 k16-steps; B fragment registers reused across the two passes.
        #pragma unroll
        for (int ks = 0; ks < 2; ks++) {
            const uint32_t kadd = ks * 32;
            uint32_t aHi[2][4], bb[4][2];

            LDSM4(aHi[0][0], aHi[0][1], aHi[0][2], aHi[0][3], sA + aoff[0] + kadd);
            LDSM4(aHi[1][0], aHi[1][1], aHi[1][2], aHi[1][3], sA + aoff[1] + kadd);

            LDSM4(bb[0][0], bb[0][1], bb[1][0], bb[1][1], sBh + boff[0] + kadd);
            LDSM4(bb[2][0], bb[2][1], bb[3][0], bb[3][1], sBh + boff[1] + kadd);
            #pragma unroll
            for (int nt = 0; nt < 4; nt++)
                #pragma unroll
                for (int mt = 0; mt < 2; mt++)
                    MMAH(acc[mt][nt], aHi[mt], bb[nt]);

            LDSM4(bb[0][0], bb[0][1], bb[1][0], bb[1][1], sBl + boff[0] + kadd);
            LDSM4(bb[2][0], bb[2][1], bb[3][0], bb[3][1], sBl + boff[1] + kadd);
            #pragma unroll
            for (int nt = 0; nt < 4; nt++)
                #pragma unroll
                for (int mt = 0; mt < 2; mt++)
                    MMAH(acc[mt][nt], aHi[mt], bb[nt]);
        }
        __syncthreads();

        if (kc < 6) stage_chunk(kc + 2, buf);
    }

    // Epilogue: bias + relu + store
    #pragma unroll
    for (int mt = 0; mt < 2; mt++) {
        int r_lo = row0 + wm * 32 + mt * 16 + q;
        int r_hi = r_lo + 8;
        #pragma unroll
        for (int nt = 0; nt < 4; nt++) {
            int n = wn * 32 + nt * 8 + tg * 2;
            float b0 = sBias[n], b1 = sBias[n + 1];
            if (r_lo < N_NODES) {
                float2 o;
                o.x = fmaxf(acc[mt][nt][0] + b0, 0.f);
                o.y = fmaxf(acc[mt][nt][1] + b1, 0.f);
                *(float2*)(out + (size_t)r_lo * F + n) = o;
            }
            if (r_hi < N_NODES) {
                float2 o;
                o.x = fmaxf(acc[mt][nt][2] + b0, 0.f);
                o.y = fmaxf(acc[mt][nt][3] + b1, 0.f);
                *(float2*)(out + (size_t)r_hi * F + n) = o;
            }
        }
    }
}

// ---------------------------------------------------------------------------
extern "C" void kernel_launch(void* const* d_in, const int* in_sizes, int n_in,
                              void* d_out, int out_size) {
    const float* x    = (const float*)d_in[0];
    const void*  eidx = d_in[1];
    const float* Wl   = (const float*)d_in[2];
    const float* Wr   = (const float*)d_in[3];
    const float* b    = (const float*)d_in[4];
    float* out = (float*)d_out;

    cudaFuncSetAttribute(gemm_kernel, cudaFuncAttributeMaxDynamicSharedMemorySize,
                         (int)GEMM_SMEM);

    prep_all_kernel<<<6250, 256>>>(x, (const int*)eidx, Wl, Wr);
    fill_kernel<<<(N_EDGES + 2047) / 2048, 256>>>(eidx);
    gather_kernel<<<(N_NODES * 32 + 255) / 256, 256>>>();
    gemm_kernel<<<N_TILES, 256, GEMM_SMEM>>>(b, out);
}

// round 16
// speedup vs baseline: 1.1747x; 1.1747x over previous
#include <cuda_runtime.h>
#include <cuda_fp16.h>
#include <cstdint>
#include <cstring>

#define N_NODES 50000
#define N_PAD   50048            // padded rows: 391 full 128-row tiles
#define N_EDGES 640000
#define F 128
#define N_TILES 391
#define BKT_CAP 128

typedef unsigned long long ull;

__device__ __forceinline__ uint32_t h2u(__half2 h) {
    uint32_t u;
    memcpy(&u, &h, 4);
    return u;
}

// Scratch (device globals). x/mean padded so tail-tile cp.async stays in-bounds.
__device__ __align__(256) __half g_xh[(size_t)N_PAD * F];        // x hi (fp16)
__device__ __align__(256) __half g_mh[(size_t)N_PAD * F];        // mean hi
__device__ __align__(256) int    g_bucket[(size_t)N_NODES * BKT_CAP];
__device__ __align__(256) int    g_deg[N_NODES];
__device__ __align__(256) __half g_Wt[128 * 256];                // W^T fp16
__device__ int g_idx64;

// ---------------------------------------------------------------------------
// prep_all: fused detect + zero_deg + prep_w + prep_x.
// ---------------------------------------------------------------------------
__global__ void __launch_bounds__(256) prep_all_kernel(
    const float* __restrict__ x,
    const int* __restrict__ e,
    const float* __restrict__ Wl,
    const float* __restrict__ Wr)
{
    const int tid = threadIdx.x;
    const int bid = blockIdx.x;
    const int gi  = bid * 256 + tid;

    if (bid == 6249 && tid == 0) {
        int nz = 0;
        #pragma unroll 8
        for (int i = 0; i < 256; i++) nz |= e[2 * i + 1];
        g_idx64 = (nz == 0) ? 1 : 0;
    }
    if (gi < N_NODES) g_deg[gi] = 0;
    if (bid < 128) {
        int n = bid, k = tid;
        float v = (k < 128) ? Wl[k * 128 + n] : Wr[(k - 128) * 128 + n];
        g_Wt[n * 256 + k] = __float2half_rn(v);
    }
    {
        float4 v = ((const float4*)x)[gi];
        __half2 h01 = __floats2half2_rn(v.x, v.y);
        __half2 h23 = __floats2half2_rn(v.z, v.w);
        uint2 sh;
        sh.x = h2u(h01); sh.y = h2u(h23);
        ((uint2*)g_xh)[gi] = sh;
    }
}

// ---------------------------------------------------------------------------
// Bucket fill: 8 edges per thread.
// ---------------------------------------------------------------------------
__global__ void __launch_bounds__(256) fill_kernel(const void* __restrict__ eidx) {
    int base = blockIdx.x * 2048 + threadIdx.x;
    const int idx64 = g_idx64;
    #pragma unroll
    for (int j = 0; j < 8; j++) {
        int e = base + j * 256;
        if (e >= N_EDGES) return;
        int src, dst;
        if (idx64) {
            const long long* p = (const long long*)eidx;
            src = (int)p[e];
            dst = (int)p[N_EDGES + e];
        } else {
            const int* p = (const int*)eidx;
            src = p[e];
            dst = p[N_EDGES + e];
        }
        int pos = atomicAdd(&g_deg[dst], 1);
        if (pos < BKT_CAP) g_bucket[(size_t)dst * BKT_CAP + pos] = src;
    }
}

// ---------------------------------------------------------------------------
// Gather: one warp per node; half-warps process even/odd neighbors, combine
// via shfl_xor(16); sub0 writes the fp16 mean.
// ---------------------------------------------------------------------------
__global__ void __launch_bounds__(256) gather_kernel() {
    int node = (blockIdx.x * 256 + threadIdx.x) >> 5;
    int lane = threadIdx.x & 31;
    if (node >= N_NODES) return;

    int deg = g_deg[node];
    int d   = min(deg, BKT_CAP);
    const int* bkt = g_bucket + (size_t)node * BKT_CAP;

    const int hl  = lane & 15;
    const int sub = lane >> 4;

    float a[8]  = {0.f, 0.f, 0.f, 0.f, 0.f, 0.f, 0.f, 0.f};
    float a2[8] = {0.f, 0.f, 0.f, 0.f, 0.f, 0.f, 0.f, 0.f};

    auto add8 = [&](float* acc, uint4 u) {
        const uint32_t w[4] = {u.x, u.y, u.z, u.w};
        #pragma unroll
        for (int p = 0; p < 4; p++) {
            __half2 hp;
            memcpy(&hp, &w[p], 4);
            float2 f = __half22float2(hp);
            acc[2 * p]     += f.x;
            acc[2 * p + 1] += f.y;
        }
    };

    for (int base = 0; base < d; base += 32) {
        int cnt = min(32, d - base);
        int s = (lane < cnt) ? bkt[base + lane] : 0;
        int j = 0;
        for (; j + 4 <= cnt; j += 4) {
            int sA = __shfl_sync(0xFFFFFFFFu, s, j + sub);
            int sB = __shfl_sync(0xFFFFFFFFu, s, j + 2 + sub);
            uint4 vA = *(const uint4*)(g_xh + (size_t)sA * F + hl * 8);
            uint4 vB = *(const uint4*)(g_xh + (size_t)sB * F + hl * 8);
            add8(a, vA);
            add8(a2, vB);
        }
        for (; j + 2 <= cnt; j += 2) {
            int sA = __shfl_sync(0xFFFFFFFFu, s, j + sub);
            uint4 vA = *(const uint4*)(g_xh + (size_t)sA * F + hl * 8);
            add8(a, vA);
        }
        if (j < cnt) {
            int sA = __shfl_sync(0xFFFFFFFFu, s, j);
            if (sub == 0) {
                uint4 vA = *(const uint4*)(g_xh + (size_t)sA * F + hl * 8);
                add8(a, vA);
            }
        }
    }

    float inv = 1.f / fmaxf((float)deg, 1.f);
    uint32_t outw[4];
    #pragma unroll
    for (int p = 0; p < 4; p++) {
        float v0 = a[2 * p] + a2[2 * p];
        float v1 = a[2 * p + 1] + a2[2 * p + 1];
        v0 += __shfl_xor_sync(0xFFFFFFFFu, v0, 16);
        v1 += __shfl_xor_sync(0xFFFFFFFFu, v1, 16);
        outw[p] = h2u(__floats2half2_rn(v0 * inv, v1 * inv));
    }
    if (sub == 0)
        *(uint4*)(g_mh + (size_t)node * F + hl * 8) =
            make_uint4(outw[0], outw[1], outw[2], outw[3]);
}

// ---------------------------------------------------------------------------
// Single-pass FP16 mma.sync GEMM: out = relu(A_hi @ W_fp16^T + b)
// Block 128m x 128n, K chunks of 64 (4 chunks), 512 threads = 16 warps.
// ~72 KB smem + <=64 regs -> 2 CTAs/SM.
// ---------------------------------------------------------------------------
#define STRIDE_B 144                // bytes per smem row (64 halves + 16B pad)
#define BUF_SZ   (128 * STRIDE_B)   // 18432 B
#define OFF_BIAS 0
#define OFF_A0   512
#define OFF_A1   (OFF_A0 + BUF_SZ)
#define OFF_B0   (OFF_A1 + BUF_SZ)
#define OFF_B1   (OFF_B0 + BUF_SZ)
#define GEMM_SMEM (OFF_B1 + BUF_SZ)   // 74240 B

#define MMAH(c, a, bb) \
    asm("mma.sync.aligned.m16n8k16.row.col.f32.f16.f16.f32 " \
        "{%0,%1,%2,%3}, {%4,%5,%6,%7}, {%8,%9}, {%0,%1,%2,%3};" \
        : "+f"((c)[0]), "+f"((c)[1]), "+f"((c)[2]), "+f"((c)[3]) \
        : "r"((a)[0]), "r"((a)[1]), "r"((a)[2]), "r"((a)[3]), \
          "r"((bb)[0]), "r"((bb)[1]))

#define LDSM4(r0, r1, r2, r3, addr) \
    asm volatile("ldmatrix.sync.aligned.m8n8.x4.shared.b16 {%0,%1,%2,%3}, [%4];" \
        : "=r"(r0), "=r"(r1), "=r"(r2), "=r"(r3) : "r"(addr))

__device__ __forceinline__ uint32_t smem_u32(const void* p) {
    uint32_t a;
    asm("{ .reg .u64 t; cvta.to.shared.u64 t, %1; cvt.u32.u64 %0, t; }" : "=r"(a) : "l"(p));
    return a;
}
__device__ __forceinline__ void cp16(uint32_t s, const void* g) {
    asm volatile("cp.async.cg.shared.global [%0], [%1], 16;" :: "r"(s), "l"(g));
}

extern __shared__ char gsm[];

__global__ void __launch_bounds__(512, 2) gemm_kernel(
    const float* __restrict__ b,
    float* __restrict__ out)
{
    const int tid  = threadIdx.x;
    const int wid  = tid >> 5;
    const int lane = tid & 31;
    const int row0 = blockIdx.x * 128;
    const int q    = lane >> 2;
    const int tg   = lane & 3;

    const int wm = wid & 3;          // m block (x32)
    const int wn = wid >> 2;         // n block (x32)

    float* sBias = (float*)(gsm + OFF_BIAS);
    if (tid < 128) sBias[tid] = b[tid];

    const uint32_t sbase = smem_u32(gsm);

    // ldmatrix per-lane offsets (rows of 64 halves = 128B + 16B pad).
    const int mat = lane >> 3;
    const int mr  = lane & 7;
    uint32_t aoff[2], boff[2];
    #pragma unroll
    for (int mt = 0; mt < 2; mt++) {
        int r = wm * 32 + mt * 16 + (mat & 1) * 8 + mr;
        aoff[mt] = (uint32_t)r * STRIDE_B + (mat >> 1) * 16;
    }
    #pragma unroll
    for (int p = 0; p < 2; p++) {
        int r = wn * 32 + p * 16 + (mat >> 1) * 8 + mr;
        boff[p] = (uint32_t)r * STRIDE_B + (mat & 1) * 16;
    }

    // Stage one K64 chunk (A + B): 1024 cp16 each, 2 per thread per array.
    auto stage_chunk = [&](int kc, int buf) {
        const uint32_t dA = sbase + (buf ? OFF_A1 : OFF_A0);
        const uint32_t dB = sbase + (buf ? OFF_B1 : OFF_B0);
        const __half* srcA = (kc < 2) ? g_mh : g_xh;
        const int cb = (kc & 1) * 64;
        #pragma unroll
        for (int j = 0; j < 2; j++) {
            int idx = tid + j * 512;        // 0..1023
            int r   = idx >> 3;
            int c4  = idx & 7;
            uint32_t doff = (uint32_t)r * STRIDE_B + c4 * 16;
            cp16(dA + doff, srcA + (size_t)(row0 + r) * F + cb + c4 * 8);
            cp16(dB + doff, g_Wt + (size_t)r * 256 + kc * 64 + c4 * 8);
        }
        asm volatile("cp.async.commit_group;" ::: "memory");
    };

    stage_chunk(0, 0);
    stage_chunk(1, 1);

    float acc[2][4][4];
    #pragma unroll
    for (int mt = 0; mt < 2; mt++)
        #pragma unroll
        for (int nt = 0; nt < 4; nt++)
            #pragma unroll
            for (int r = 0; r < 4; r++) acc[mt][nt][r] = 0.f;

    for (int kc = 0; kc < 4; kc++) {
        const int buf = kc & 1;
        if (kc < 3) {
            asm volatile("cp.async.wait_group 1;" ::: "memory");
        } else {
            asm volatile("cp.async.wait_group 0;" ::: "memory");
        }
        __syncthreads();

        const uint32_t sA = sbase + (buf ? OFF_A1 : OFF_A0);
        const uint32_t sB = sbase + (buf ? OFF_B1 : OFF_B0);

        // 4 k16-steps: 4 ldmatrix.x4 + 8 independent MMAs
        #pragma unroll
        for (int ks = 0; ks < 4; ks++) {
            const uint32_t kadd = ks * 32;
            uint32_t aHi[2][4], bb[4][2];

            LDSM4(aHi[0][0], aHi[0][1], aHi[0][2], aHi[0][3], sA + aoff[0] + kadd);
            LDSM4(aHi[1][0], aHi[1][1], aHi[1][2], aHi[1][3], sA + aoff[1] + kadd);
            LDSM4(bb[0][0], bb[0][1], bb[1][0], bb[1][1], sB + boff[0] + kadd);
            LDSM4(bb[2][0], bb[2][1], bb[3][0], bb[3][1], sB + boff[1] + kadd);

            #pragma unroll
            for (int nt = 0; nt < 4; nt++)
                #pragma unroll
                for (int mt = 0; mt < 2; mt++)
                    MMAH(acc[mt][nt], aHi[mt], bb[nt]);
        }
        __syncthreads();

        if (kc < 2) stage_chunk(kc + 2, buf);
    }

    // Epilogue: bias + relu + store
    #pragma unroll
    for (int mt = 0; mt < 2; mt++) {
        int r_lo = row0 + wm * 32 + mt * 16 + q;
        int r_hi = r_lo + 8;
        #pragma unroll
        for (int nt = 0; nt < 4; nt++) {
            int n = wn * 32 + nt * 8 + tg * 2;
            float b0 = sBias[n], b1 = sBias[n + 1];
            if (r_lo < N_NODES) {
                float2 o;
                o.x = fmaxf(acc[mt][nt][0] + b0, 0.f);
                o.y = fmaxf(acc[mt][nt][1] + b1, 0.f);
                *(float2*)(out + (size_t)r_lo * F + n) = o;
            }
            if (r_hi < N_NODES) {
                float2 o;
                o.x = fmaxf(acc[mt][nt][2] + b0, 0.f);
                o.y = fmaxf(acc[mt][nt][3] + b1, 0.f);
                *(float2*)(out + (size_t)r_hi * F + n) = o;
            }
        }
    }
}

// ---------------------------------------------------------------------------
extern "C" void kernel_launch(void* const* d_in, const int* in_sizes, int n_in,
                              void* d_out, int out_size) {
    const float* x    = (const float*)d_in[0];
    const void*  eidx = d_in[1];
    const float* Wl   = (const float*)d_in[2];
    const float* Wr   = (const float*)d_in[3];
    const float* b    = (const float*)d_in[4];
    float* out = (float*)d_out;

    cudaFuncSetAttribute(gemm_kernel, cudaFuncAttributeMaxDynamicSharedMemorySize,
                         (int)GEMM_SMEM);

    prep_all_kernel<<<6250, 256>>>(x, (const int*)eidx, Wl, Wr);
    fill_kernel<<<(N_EDGES + 2047) / 2048, 256>>>(eidx);
    gather_kernel<<<(N_NODES * 32 + 255) / 256, 256>>>();
    gemm_kernel<<<N_TILES, 512, GEMM_SMEM>>>(b, out);
}